// round 7
// baseline (speedup 1.0000x reference)
#include <cuda_runtime.h>
#include <cuda_bf16.h>
#include <cstdint>

// Problem constants
#define BB   128   // batch
#define SS   37    // sensors
#define TT   2048  // time steps
#define DD   256   // d_model
#define STT  8     // static feats
#define CC   2     // classes
#define MER  264   // merged = DD + STT
#define NF   74    // 2*SS features

#define NT   1024       // threads per block (forces <=64 regs)
#define HALFT 512
#define RF4  (TT / 4)   // 512 float4 per sensor row

// per-warp partial layout: 76 quantities x 4 partials, padded stride
#define PW   312        // floats per warp row (76*4=304, pad to 312)

// Phase-2 merge GEMV split
#define G2   12
#define Q2   66              // 66*4 = 264 columns
#define KI2  (MER / G2)      // 22

__device__ __forceinline__ float wredf(float v) {
    #pragma unroll
    for (int o = 16; o; o >>= 1) v += __shfl_xor_sync(0xffffffffu, v, o);
    return v;
}

// 3-level reduction: lanes 0-3 end with 4 disjoint partial sums
__device__ __forceinline__ float wred3(float v) {
    v += __shfl_xor_sync(0xffffffffu, v, 16);
    v += __shfl_xor_sync(0xffffffffu, v, 8);
    v += __shfl_xor_sync(0xffffffffu, v, 4);
    return v;
}

__device__ __forceinline__ void pf_l2(const void* p) {
    asm volatile("prefetch.global.L2 [%0];" :: "l"(p));
}

__global__ __launch_bounds__(NT, 1)
void fused_kernel(const float* __restrict__ x,
                  const int*   __restrict__ smask,
                  const float* __restrict__ tim,
                  const float* __restrict__ stat,
                  const float* __restrict__ Ws,   // [NF, DD]
                  const float* __restrict__ bs,   // [DD]
                  const float* __restrict__ Wt,   // [1, DD]
                  const float* __restrict__ bt,   // [DD]
                  const float* __restrict__ Wst,  // [STT, STT]
                  const float* __restrict__ bst,  // [STT]
                  const float* __restrict__ Wm,   // [MER, MER]
                  const float* __restrict__ bm,   // [MER]
                  const float* __restrict__ Wc,   // [MER, CC]
                  const float* __restrict__ bc,   // [CC]
                  float* __restrict__ out) {
    const int b    = blockIdx.x;
    const int tid  = threadIdx.x;
    const int w    = tid >> 5;
    const int lane = tid & 31;
    const int k    = tid & (HALFT - 1);  // t-chunk index (float4 position)
    const int half = tid >> 9;           // 0: even sensors (+36), 1: odd sensors

    __shared__ float  sW[32 * PW];      // per-warp partials [warp][76*4]  (~40KB)
    __shared__ float4 sNZ[HALFT];       // cross-half nz staging (8KB)
    __shared__ float  sAll[80];         // 74 feature sums + msum + tmsum
    __shared__ float  comb[MER];
    __shared__ float4 sH4[G2 * Q2];     // merge partials [g][q]
    __shared__ float  outc[CC];

    // zero per-warp partial rows (cells not written by a warp stay 0)
    for (int i = tid; i < 32 * PW; i += NT) sW[i] = 0.f;
    if (tid < CC) outc[tid] = 0.f;

    // ---- L2 prefetch of all weights (spread across the grid), fire-and-forget ----
    {
        unsigned r = (unsigned)b * NT + tid;
        const unsigned LWs = (NF * DD * 4) / 128;     // 592
        const unsigned LWm = (MER * MER * 4) / 128;   // 2178
        if (r < LWs) { pf_l2((const char*)Ws + r * 128u); }
        else { r -= LWs;
        if (r < LWm) { pf_l2((const char*)Wm + r * 128u); }
        else { r -= LWm;
        if (r < 17) { pf_l2((const char*)Wc + r * 128u); }
        else { r -= 17;
        if (r < 8) { pf_l2((const char*)bs + r * 128u); }
        else { r -= 8;
        if (r < 8) { pf_l2((const char*)bt + r * 128u); }
        else { r -= 8;
        if (r < 8) { pf_l2((const char*)Wt + r * 128u); }
        else { r -= 8;
        if (r < 9) { pf_l2((const char*)bm + r * 128u); }
        else { r -= 9;
        if (r < 32) { pf_l2((const char*)stat + r * 128u); }
        else { r -= 32;
        if (r < 2) { pf_l2((const char*)Wst + r * 128u); }
        else { r -= 2;
        if (r < 1) { pf_l2((const char*)bst); }
        else { r -= 1;
        if (r < 1) { pf_l2((const char*)bc); }
        }}}}}}}}}}
    }
    __syncthreads();   // sW zero-init visible before per-warp writes

    // ================= Phase 1: streaming reduction over [SS, TT] =================
    const size_t baseb = (size_t)b * SS * TT;
    const float4* __restrict__ xp = (const float4*)(x     + baseb);
    const int4*   __restrict__ mp = (const int4*)  (smask + baseb);

    float* myrow = &sW[w * PW];

    // combined nonzero accumulators (fabs(x) + mask; >0 iff any nonzero)
    float nz0 = 0.f, nz1 = 0.f, nz2 = 0.f, nz3 = 0.f;

    // 18 sensor-pairs: this thread handles sensor s = 2c + half at t-chunk k
    #pragma unroll
    for (int c = 0; c < 18; ++c) {
        const int s = 2 * c + half;
        const float4 xv = xp[s * RF4 + k];
        const int4   mv = mp[s * RF4 + k];

        float ax = (xv.x + xv.y) + (xv.z + xv.w);
        float am = (float)((mv.x + mv.y) + (mv.z + mv.w));

        nz0 += fabsf(xv.x) + (float)mv.x;
        nz1 += fabsf(xv.y) + (float)mv.y;
        nz2 += fabsf(xv.z) + (float)mv.z;
        nz3 += fabsf(xv.w) + (float)mv.w;

        ax = wred3(ax);
        am = wred3(am);
        if (lane < 4) {
            myrow[s * 4 + lane]        = ax;
            myrow[(SS + s) * 4 + lane] = am;
        }
    }

    // leftover sensor 36 (lower half only; warp-uniform branch)
    if (half == 0) {
        const float4 xv = xp[36 * RF4 + k];
        const int4   mv = mp[36 * RF4 + k];
        float ax = (xv.x + xv.y) + (xv.z + xv.w);
        float am = (float)((mv.x + mv.y) + (mv.z + mv.w));
        nz0 += fabsf(xv.x) + (float)mv.x;
        nz1 += fabsf(xv.y) + (float)mv.y;
        nz2 += fabsf(xv.z) + (float)mv.z;
        nz3 += fabsf(xv.w) + (float)mv.w;
        ax = wred3(ax);
        am = wred3(am);
        if (lane < 4) {
            myrow[36 * 4 + lane]        = ax;
            myrow[(SS + 36) * 4 + lane] = am;
        }
        sNZ[k] = make_float4(nz0, nz1, nz2, nz3);
    }
    __syncthreads();

    // upper half combines nz across the thread pair and computes msum/tmsum
    if (half == 1) {
        const float4 o  = sNZ[k];
        const float4 tv = ((const float4*)(tim + (size_t)b * TT))[k];
        float ms = 0.f, tm = 0.f;
        if (nz0 + o.x > 0.f) { ms += 1.f; tm += tv.x; }
        if (nz1 + o.y > 0.f) { ms += 1.f; tm += tv.y; }
        if (nz2 + o.z > 0.f) { ms += 1.f; tm += tv.z; }
        if (nz3 + o.w > 0.f) { ms += 1.f; tm += tv.w; }
        ms = wred3(ms);
        tm = wred3(tm);
        if (lane < 4) {
            myrow[74 * 4 + lane] = ms;
            myrow[75 * 4 + lane] = tm;
        }
    }
    __syncthreads();

    // -------- final combine: 76 outputs, 32 warp-rows x 4 partials each --------
    if (tid < 76) {
        float acc = 0.f;
        #pragma unroll
        for (int w2 = 0; w2 < 32; ++w2) {
            const float4 p = *(const float4*)&sW[w2 * PW + tid * 4];
            acc += (p.x + p.y) + (p.z + p.w);
        }
        sAll[tid] = acc;
    }
    __syncthreads();

    // ================= Phase 2: per-batch tail (L2-warm) =================
    const float msum  = sAll[74];
    const float tmsum = sAll[75];
    const float inv   = 1.f / fmaxf(msum, 1e-9f);

    // ---- Phase A: comb[MER] ----
    if (tid < DD) {
        float acc = 0.f;
        #pragma unroll 8
        for (int f = 0; f < NF; ++f) acc += sAll[f] * Ws[f * DD + tid];
        acc += msum * (bs[tid] + bt[tid]) + tmsum * Wt[tid];
        comb[tid] = acc * inv;
    } else if (tid < MER) {
        const int j = tid - DD;
        float acc = bst[j];
        #pragma unroll
        for (int i = 0; i < STT; ++i) acc += stat[b * STT + i] * Wst[i * STT + j];
        comb[tid] = acc;
    }
    __syncthreads();

    // ---- Phase B: merge GEMV, split-i (G2 groups), float4 columns ----
    if (tid < G2 * Q2) {
        const int q  = tid % Q2;   // column quad
        const int gg = tid / Q2;   // i-group
        const float4* __restrict__ Wm4 = (const float4*)Wm;  // row = 66 quads
        float4 acc = make_float4(0.f, 0.f, 0.f, 0.f);
        #pragma unroll
        for (int kk = 0; kk < KI2; ++kk) {
            const int i = gg * KI2 + kk;
            const float  c  = comb[i];
            const float4 wv = Wm4[i * Q2 + q];
            acc.x += c * wv.x;
            acc.y += c * wv.y;
            acc.z += c * wv.z;
            acc.w += c * wv.w;
        }
        sH4[gg * Q2 + q] = acc;
    }
    __syncthreads();

    // ---- Phase C: reduce partials, ReLU, classifier ----
    float p0 = 0.f, p1 = 0.f;
    if (tid < MER) {
        const float* sH = (const float*)sH4;   // [g][264]
        float t = bm[tid];
        #pragma unroll
        for (int gg = 0; gg < G2; ++gg) t += sH[gg * MER + tid];
        const float h = fmaxf(t, 0.f);
        p0 = h * Wc[tid * CC + 0];
        p1 = h * Wc[tid * CC + 1];
    }
    p0 = wredf(p0);
    p1 = wredf(p1);
    if (lane == 0) {
        atomicAdd(&outc[0], p0);
        atomicAdd(&outc[1], p1);
    }
    __syncthreads();

    if (tid < CC) out[b * CC + tid] = outc[tid] + bc[tid];
}

// ---------------- launch ----------------
extern "C" void kernel_launch(void* const* d_in, const int* in_sizes, int n_in,
                              void* d_out, int out_size) {
    const float* x     = (const float*)d_in[0];
    const float* stat  = (const float*)d_in[1];
    const float* tim   = (const float*)d_in[2];
    const int*   smask = (const int*)  d_in[3];
    const float* Ws    = (const float*)d_in[4];
    const float* bs    = (const float*)d_in[5];
    const float* Wt    = (const float*)d_in[6];
    const float* bt    = (const float*)d_in[7];
    const float* Wst   = (const float*)d_in[8];
    const float* bst   = (const float*)d_in[9];
    const float* Wm    = (const float*)d_in[10];
    const float* bm    = (const float*)d_in[11];
    const float* Wc    = (const float*)d_in[12];
    const float* bc    = (const float*)d_in[13];
    float* out = (float*)d_out;

    fused_kernel<<<BB, NT>>>(x, smask, tim, stat, Ws, bs, Wt, bt,
                             Wst, bst, Wm, bm, Wc, bc, out);
}